// round 7
// baseline (speedup 1.0000x reference)
#include <cuda_runtime.h>
#include <math.h>
#include <float.h>
#include <stdint.h>

#define NN 100000
#define NE 800000
#define NG 64
#define NSCAN_BLK 98   // ceil(NN/1024)

// ---------------- scratch pool (device globals; resolved device-side) ----------------
__device__ float g_B0[NN * 192];   // x1_res
__device__ float g_B1[NN * 192];   // agg (gather target)
__device__ float g_B2[NN * 256];   // h -> c -> tmp -> t
__device__ float g_B3[NN * 192];   // hw -> gate -> t2
__device__ float g_B4[NN * 192];   // h2 -> z
__device__ float g_B5[NN * 192];   // c2 -> z1_res
__device__ float g_B6[NN * 192];   // x1res+pe3 -> z1res+pe3
__device__ float g_dinv[NN];
__device__ float g_small[2 * NG * 192];  // zg | zgw
__device__ int   g_rowptr[NN + 1];
__device__ int   g_pos[NN];
__device__ int   g_bsum[128];
__device__ int   g_gstart[NG + 1];
__device__ int   g_csrc[NE];

#define SEL_ZG   16
#define SEL_ZGW  19

__device__ __forceinline__ float* scratch(int id) {
    switch (id) {
        case 0:  return g_B0;
        case 1:  return g_B1;
        case 2:  return g_B2;
        case 3:  return g_B3;
        case 4:  return g_B4;
        case 5:  return g_B5;
        case 6:  return g_B6;
        case SEL_ZG:   return g_small;
        case SEL_ZGW:  return g_small + NG * 192;
        default: return nullptr;
    }
}

// ---------------- CSR build ----------------
// zero degree counters + graph segment starts (batch is sorted)
__global__ void init_kernel(const int* __restrict__ batch) {
    int i = blockIdx.x * blockDim.x + threadIdx.x;
    if (i < NN) g_pos[i] = 0;
    if (i <= NG) {
        int lo = 0, hi = NN;
        while (lo < hi) {
            int mid = (lo + hi) >> 1;
            if (batch[mid] < i) lo = mid + 1; else hi = mid;
        }
        g_gstart[i] = lo;
    }
}

__global__ void count_deg_kernel(const int* __restrict__ dst) {
    int e = blockIdx.x * blockDim.x + threadIdx.x;
    if (e < NE) atomicAdd(&g_pos[dst[e]], 1);
}

__global__ void scan1_kernel() {
    __shared__ int s[1024];
    int tid = threadIdx.x;
    int idx = blockIdx.x * 1024 + tid;
    int v = (idx < NN) ? g_pos[idx] : 0;
    if (idx < NN) g_dinv[idx] = rsqrtf((float)v + 1.0f);
    s[tid] = v;
    __syncthreads();
    for (int off = 1; off < 1024; off <<= 1) {
        int t = (tid >= off) ? s[tid - off] : 0;
        __syncthreads();
        s[tid] += t;
        __syncthreads();
    }
    if (idx < NN) g_rowptr[idx] = s[tid] - v;
    if (tid == 1023) g_bsum[blockIdx.x] = s[1023];
}

__global__ void scan2_kernel() {
    __shared__ int s[128];
    int tid = threadIdx.x;
    int v = (tid < NSCAN_BLK) ? g_bsum[tid] : 0;
    s[tid] = v;
    __syncthreads();
    for (int off = 1; off < 128; off <<= 1) {
        int t = (tid >= off) ? s[tid - off] : 0;
        __syncthreads();
        s[tid] += t;
        __syncthreads();
    }
    if (tid < NSCAN_BLK) g_bsum[tid] = s[tid] - v;
    if (tid == 127) g_rowptr[NN] = s[127];
}

__global__ void scan3_kernel() {
    int idx = blockIdx.x * 1024 + threadIdx.x;
    if (idx < NN) {
        int r = g_rowptr[idx] + g_bsum[blockIdx.x];
        g_rowptr[idx] = r;
        g_pos[idx] = r;
    }
}

__global__ void csr_fill_kernel(const int* __restrict__ src, const int* __restrict__ dst) {
    int e = blockIdx.x * blockDim.x + threadIdx.x;
    if (e >= NE) return;
    int p = atomicAdd(&g_pos[dst[e]], 1);
    g_csrc[p] = src[e];
}

// ---------------- gather kernels (CSR, no atomics) ----------------
__global__ void gather_add_kernel(const float* __restrict__ xext, int xSel,
                                  int aggSel, int D4, int D, int total) {
    int tid = blockIdx.x * blockDim.x + threadIdx.x;
    if (tid >= total) return;
    const float* x = xext ? xext : scratch(xSel);
    float* agg = scratch(aggSel);
    int i = tid / D4;
    int c = (tid - i * D4) << 2;
    int beg = g_rowptr[i], end = g_rowptr[i + 1];
    float4 acc = make_float4(0.f, 0.f, 0.f, 0.f);
    for (int e = beg; e < end; e++) {
        int s = g_csrc[e];
        float4 v = *(const float4*)(x + (size_t)s * D + c);
        acc.x += v.x; acc.y += v.y; acc.z += v.z; acc.w += v.w;
    }
    *(float4*)(agg + (size_t)i * D + c) = acc;
}

// fused GCN: out = relu(dinv[i]*sum(hw[s]*dinv[s]) + hw[i]*dinv[i]^2 + b) [+ add1 + add2]
__global__ void gather_gcn_kernel(int hwSel, const float* __restrict__ b,
                                  int outSel, int add1Sel, int add2Sel, int total) {
    int tid = blockIdx.x * blockDim.x + threadIdx.x;
    if (tid >= total) return;
    const float* hw = scratch(hwSel);
    float* out = scratch(outSel);
    int i = tid / 48;
    int c = (tid - i * 48) << 2;
    int beg = g_rowptr[i], end = g_rowptr[i + 1];
    float4 acc = make_float4(0.f, 0.f, 0.f, 0.f);
    for (int e = beg; e < end; e++) {
        int s = g_csrc[e];
        float w = g_dinv[s];
        float4 v = *(const float4*)(hw + (size_t)s * 192 + c);
        acc.x += v.x * w; acc.y += v.y * w; acc.z += v.z * w; acc.w += v.w * w;
    }
    float di = g_dinv[i];
    float dii = di * di;
    float4 sv = *(const float4*)(hw + (size_t)i * 192 + c);
    float4 bb = *(const float4*)(b + c);
    float4 o;
    size_t idx = (size_t)i * 192 + c;
    o.x = fmaxf(acc.x * di + sv.x * dii + bb.x, 0.f);
    o.y = fmaxf(acc.y * di + sv.y * dii + bb.y, 0.f);
    o.z = fmaxf(acc.z * di + sv.z * dii + bb.z, 0.f);
    o.w = fmaxf(acc.w * di + sv.w * dii + bb.w, 0.f);
    if (add1Sel >= 0) {
        float4 a1 = *(const float4*)(scratch(add1Sel) + idx);
        float4 a2 = *(const float4*)(scratch(add2Sel) + idx);
        o.x += a1.x + a2.x; o.y += a1.y + a2.y;
        o.z += a1.z + a2.z; o.w += a1.w + a2.w;
    }
    *(float4*)(out + idx) = o;
}

// bcast GCN; dual output: out = z1res, out2 = z1res + pe3
__global__ void gather_gcn_bcast_kernel(int zgwSel, const int* __restrict__ batch,
                                        const float* __restrict__ b,
                                        int outSel, const float* __restrict__ pe,
                                        int out2Sel, int total) {
    int tid = blockIdx.x * blockDim.x + threadIdx.x;
    if (tid >= total) return;
    const float* zgw = scratch(zgwSel);
    float* out = scratch(outSel);
    int i = tid / 48;
    int c = (tid - i * 48) << 2;
    int beg = g_rowptr[i], end = g_rowptr[i + 1];
    float4 acc = make_float4(0.f, 0.f, 0.f, 0.f);
    for (int e = beg; e < end; e++) {
        int s = g_csrc[e];
        float w = g_dinv[s];
        float4 v = *(const float4*)(zgw + (size_t)batch[s] * 192 + c);
        acc.x += v.x * w; acc.y += v.y * w; acc.z += v.z * w; acc.w += v.w * w;
    }
    float di = g_dinv[i];
    float dii = di * di;
    float4 sv = *(const float4*)(zgw + (size_t)batch[i] * 192 + c);
    float4 bb = *(const float4*)(b + c);
    float4 o;
    size_t idx = (size_t)i * 192 + c;
    o.x = fmaxf(acc.x * di + sv.x * dii + bb.x, 0.f);
    o.y = fmaxf(acc.y * di + sv.y * dii + bb.y, 0.f);
    o.z = fmaxf(acc.z * di + sv.z * dii + bb.z, 0.f);
    o.w = fmaxf(acc.w * di + sv.w * dii + bb.w, 0.f);
    *(float4*)(out + idx) = o;
    float4 p = *(const float4*)(pe + (size_t)i * 64 + (c & 63));
    float4 o2 = make_float4(o.x + p.x, o.y + p.y, o.z + p.z, o.w + p.w);
    *(float4*)(scratch(out2Sel) + idx) = o2;
}

// ---------------- fused attention: one block per graph, thread = feature ----------------
__global__ void att_fused_kernel(int gateSel, int zSel) {
    int gph = blockIdx.x;
    int f = threadIdx.x;   // 0..191
    const float* gate = scratch(gateSel);
    const float* z = scratch(zSel);
    float* zg = scratch(SEL_ZG);
    int n0 = g_gstart[gph], n1 = g_gstart[gph + 1];
    if (n0 >= n1) { zg[gph * 192 + f] = 0.f; return; }

    float m0 = -FLT_MAX, m1 = -FLT_MAX, m2 = -FLT_MAX, m3 = -FLT_MAX;
    int n = n0;
    for (; n + 3 < n1; n += 4) {
        m0 = fmaxf(m0, gate[(size_t)(n + 0) * 192 + f]);
        m1 = fmaxf(m1, gate[(size_t)(n + 1) * 192 + f]);
        m2 = fmaxf(m2, gate[(size_t)(n + 2) * 192 + f]);
        m3 = fmaxf(m3, gate[(size_t)(n + 3) * 192 + f]);
    }
    for (; n < n1; n++) m0 = fmaxf(m0, gate[(size_t)n * 192 + f]);
    float m = fmaxf(fmaxf(m0, m1), fmaxf(m2, m3));

    float es0 = 0.f, es1 = 0.f, ez0 = 0.f, ez1 = 0.f;
    n = n0;
    for (; n + 1 < n1; n += 2) {
        size_t i0 = (size_t)n * 192 + f, i1 = (size_t)(n + 1) * 192 + f;
        float e0 = expf(gate[i0] - m);
        float e1 = expf(gate[i1] - m);
        es0 += e0; ez0 += e0 * z[i0];
        es1 += e1; ez1 += e1 * z[i1];
    }
    if (n < n1) {
        size_t i0 = (size_t)n * 192 + f;
        float e0 = expf(gate[i0] - m);
        es0 += e0; ez0 += e0 * z[i0];
    }
    zg[gph * 192 + f] = (ez0 + ez1) / (es0 + es1);
}

// ---------------- TF32 tensor-core GEMM (double-buffered) ----------------
// BM=192, BN=64, BK=16; 8 warps as 4(M)x2(N), each 48x32. mma.m16n8k8 tf32.
__device__ __forceinline__ uint32_t f2tf(float f) {
    uint32_t u;
    asm("cvt.rna.tf32.f32 %0, %1;" : "=r"(u) : "f"(f));
    return u;
}

__device__ __forceinline__ void mma_tf32(float& c0, float& c1, float& c2, float& c3,
                                         uint32_t a0, uint32_t a1, uint32_t a2, uint32_t a3,
                                         uint32_t b0, uint32_t b1) {
    asm volatile(
        "mma.sync.aligned.m16n8k8.row.col.f32.tf32.tf32.f32 "
        "{%0,%1,%2,%3},{%4,%5,%6,%7},{%8,%9},{%0,%1,%2,%3};\n"
        : "+f"(c0), "+f"(c1), "+f"(c2), "+f"(c3)
        : "r"(a0), "r"(a1), "r"(a2), "r"(a3), "r"(b0), "r"(b1));
}

__global__ __launch_bounds__(256)
void tgemm_kernel(int M, int N, int K,
                  const float* __restrict__ Aext, int Asel,
                  const float* __restrict__ B,
                  const float* __restrict__ bias,
                  int resSel,
                  float* __restrict__ Cext, int Csel,
                  int relu,
                  int c2Sel, const float* __restrict__ peAdd) {
    __shared__ uint32_t As[2][192][20];  // 30.7KB; stride 20 -> conflict-free frag loads
    __shared__ uint32_t Bs[2][16][72];   //  9.2KB; stride 72 -> conflict-free frag loads

    const float* A = Aext ? Aext : scratch(Asel);
    float* C = Cext ? Cext : scratch(Csel);
    const float* res = (resSel >= 0) ? scratch(resSel) : nullptr;

    int tid = threadIdx.x;
    int bm0 = blockIdx.y * 192, bn0 = blockIdx.x * 64;
    int lane = tid & 31, wid = tid >> 5;
    int g = lane >> 2, t4 = lane & 3;
    int wm = (wid & 3) * 48;    // 4 warps down M, 48 rows each
    int wn = (wid >> 2) * 32;   // 2 warps across N

    // A: 192x16 floats = 768 float4, 3 per thread
    int aRow[3], aCol[3];
    bool aOk[3];
#pragma unroll
    for (int q = 0; q < 3; q++) {
        int fid = tid + 256 * q;
        aRow[q] = fid >> 2;
        aCol[q] = (fid & 3) << 2;
        aOk[q] = (bm0 + aRow[q]) < M;
    }
    int bRow = tid >> 4, bCol = (tid & 15) << 2;
    const float* Bptr = B + (size_t)bRow * N + bn0 + bCol;

    float acc[3][4][4];
#pragma unroll
    for (int mi = 0; mi < 3; mi++)
#pragma unroll
        for (int ni = 0; ni < 4; ni++)
#pragma unroll
            for (int q = 0; q < 4; q++) acc[mi][ni][q] = 0.f;

    float4 pa[3];
    float4 pb;
#pragma unroll
    for (int q = 0; q < 3; q++) {
        pa[q] = make_float4(0.f, 0.f, 0.f, 0.f);
        if (aOk[q]) pa[q] = *(const float4*)(A + (size_t)(bm0 + aRow[q]) * K + aCol[q]);
    }
    pb = *(const float4*)Bptr;

    // stage tile 0
#pragma unroll
    for (int q = 0; q < 3; q++) {
        As[0][aRow[q]][aCol[q] + 0] = f2tf(pa[q].x);
        As[0][aRow[q]][aCol[q] + 1] = f2tf(pa[q].y);
        As[0][aRow[q]][aCol[q] + 2] = f2tf(pa[q].z);
        As[0][aRow[q]][aCol[q] + 3] = f2tf(pa[q].w);
    }
    Bs[0][bRow][bCol + 0] = f2tf(pb.x); Bs[0][bRow][bCol + 1] = f2tf(pb.y);
    Bs[0][bRow][bCol + 2] = f2tf(pb.z); Bs[0][bRow][bCol + 3] = f2tf(pb.w);
    __syncthreads();

    int buf = 0;
    for (int k0 = 0; k0 < K; k0 += 16) {
        bool more = (k0 + 16) < K;
        if (more) {
#pragma unroll
            for (int q = 0; q < 3; q++)
                if (aOk[q]) pa[q] = *(const float4*)(A + (size_t)(bm0 + aRow[q]) * K + k0 + 16 + aCol[q]);
            pb = *(const float4*)(Bptr + (size_t)(k0 + 16) * N);
        }

#pragma unroll
        for (int ks = 0; ks < 16; ks += 8) {
            uint32_t af[3][4], bf[4][2];
#pragma unroll
            for (int mi = 0; mi < 3; mi++) {
                int rb = wm + mi * 16;
                af[mi][0] = As[buf][rb + g][ks + t4];
                af[mi][1] = As[buf][rb + g + 8][ks + t4];
                af[mi][2] = As[buf][rb + g][ks + t4 + 4];
                af[mi][3] = As[buf][rb + g + 8][ks + t4 + 4];
            }
#pragma unroll
            for (int ni = 0; ni < 4; ni++) {
                int cb = wn + ni * 8 + g;
                bf[ni][0] = Bs[buf][ks + t4][cb];
                bf[ni][1] = Bs[buf][ks + t4 + 4][cb];
            }
#pragma unroll
            for (int mi = 0; mi < 3; mi++)
#pragma unroll
                for (int ni = 0; ni < 4; ni++)
                    mma_tf32(acc[mi][ni][0], acc[mi][ni][1], acc[mi][ni][2], acc[mi][ni][3],
                             af[mi][0], af[mi][1], af[mi][2], af[mi][3],
                             bf[ni][0], bf[ni][1]);
        }

        if (more) {
            int nb = buf ^ 1;
#pragma unroll
            for (int q = 0; q < 3; q++) {
                As[nb][aRow[q]][aCol[q] + 0] = f2tf(pa[q].x);
                As[nb][aRow[q]][aCol[q] + 1] = f2tf(pa[q].y);
                As[nb][aRow[q]][aCol[q] + 2] = f2tf(pa[q].z);
                As[nb][aRow[q]][aCol[q] + 3] = f2tf(pa[q].w);
            }
            Bs[nb][bRow][bCol + 0] = f2tf(pb.x); Bs[nb][bRow][bCol + 1] = f2tf(pb.y);
            Bs[nb][bRow][bCol + 2] = f2tf(pb.z); Bs[nb][bRow][bCol + 3] = f2tf(pb.w);
            __syncthreads();
        }
        buf ^= 1;
    }

    float* C2 = (c2Sel >= 0) ? scratch(c2Sel) : nullptr;
#pragma unroll
    for (int mi = 0; mi < 3; mi++) {
#pragma unroll
        for (int ni = 0; ni < 4; ni++) {
            int col = bn0 + wn + ni * 8 + 2 * t4;
            float bx = bias ? bias[col] : 0.f;
            float by = bias ? bias[col + 1] : 0.f;
#pragma unroll
            for (int h = 0; h < 2; h++) {
                int r = bm0 + wm + mi * 16 + g + h * 8;
                if (r >= M) continue;
                float v0 = acc[mi][ni][2 * h + 0] + bx;
                float v1 = acc[mi][ni][2 * h + 1] + by;
                if (relu) { v0 = fmaxf(v0, 0.f); v1 = fmaxf(v1, 0.f); }
                if (res) {
                    v0 += res[(size_t)r * N + col];
                    v1 += res[(size_t)r * N + col + 1];
                }
                *(float2*)(C + (size_t)r * N + col) = make_float2(v0, v1);
                if (C2) {
                    int pc = col & 63;
                    float p0 = peAdd[(size_t)r * 64 + pc];
                    float p1 = peAdd[(size_t)r * 64 + pc + 1];
                    *(float2*)(C2 + (size_t)r * N + col) = make_float2(v0 + p0, v1 + p1);
                }
            }
        }
    }
}

// ---------------- launch helpers ----------------
static inline void launch_gemm(int M, int N, int K,
                               const float* Aext, int Asel, const float* B,
                               const float* bias, int resSel,
                               float* Cext, int Csel, int relu,
                               int c2Sel = -1, const float* peAdd = nullptr) {
    dim3 grid((N + 63) / 64, (M + 191) / 192);
    tgemm_kernel<<<grid, 256>>>(M, N, K, Aext, Asel, B, bias, resSel, Cext, Csel,
                                relu, c2Sel, peAdd);
}

extern "C" void kernel_launch(void* const* d_in, const int* in_sizes, int n_in,
                              void* d_out, int out_size) {
    const float* x1    = (const float*)d_in[0];
    const float* x2    = (const float*)d_in[1];
    const float* pe    = (const float*)d_in[2];
    const int*   ei    = (const int*)d_in[3];
    const int*   batch = (const int*)d_in[4];
    const float *Wc  = (const float*)d_in[5],  *bc  = (const float*)d_in[6];
    const float *Wmf = (const float*)d_in[7],  *bmf = (const float*)d_in[8];
    const float *Wgf = (const float*)d_in[9],  *bgf = (const float*)d_in[10];
    const float *Wmc = (const float*)d_in[11], *bmc = (const float*)d_in[12];
    const float *Wgc = (const float*)d_in[13], *bgc = (const float*)d_in[14];
    const float *Wa1 = (const float*)d_in[15], *ba1 = (const float*)d_in[16];
    const float *Wa2 = (const float*)d_in[17], *ba2 = (const float*)d_in[18];
    const float *Wgd = (const float*)d_in[19], *bgd = (const float*)d_in[20];
    const float *Wd1 = (const float*)d_in[21], *bd1 = (const float*)d_in[22];
    const float *Wd2 = (const float*)d_in[23], *bd2 = (const float*)d_in[24];
    const float *Wd3 = (const float*)d_in[25], *bd3 = (const float*)d_in[26];
    float* out = (float*)d_out;

    const int* src = ei;
    const int* dst = ei + NE;

    const int NODE192 = NN * 48;
    const int NODE32  = NN * 8;
    const int BLK = 256;

    // ---- CSR build + graph segment bounds ----
    init_kernel<<<(NN + BLK - 1) / BLK, BLK>>>(batch);
    count_deg_kernel<<<(NE + BLK - 1) / BLK, BLK>>>(dst);
    scan1_kernel<<<NSCAN_BLK, 1024>>>();
    scan2_kernel<<<1, 128>>>();
    scan3_kernel<<<NSCAN_BLK, 1024>>>();
    csr_fill_kernel<<<(NE + BLK - 1) / BLK, BLK>>>(src, dst);

    // ---- encoder ----
    // B0 = x1_res; B6 = x1_res + pe3 (dual-output epilogue)
    launch_gemm(NN, 192, 384, x1, -1, Wc, bc, -1, nullptr, 0, 1, 6, pe);
    gather_add_kernel<<<(NODE192 + BLK - 1) / BLK, BLK>>>(nullptr, 6, 1, 48, 192, NODE192);
    launch_gemm(NN, 256, 192, nullptr, 1, Wmf, bmf, -1, nullptr, 2, 1);
    launch_gemm(NN, 192, 256, nullptr, 2, Wgf, nullptr, -1, nullptr, 3, 0);
    gather_gcn_kernel<<<(NODE192 + BLK - 1) / BLK, BLK>>>(3, bgf, 4, -1, -1, NODE192);
    gather_add_kernel<<<(NODE32 + BLK - 1) / BLK, BLK>>>(x2, -1, 1, 8, 32, NODE32);
    launch_gemm(NN, 64, 32, nullptr, 1, Wmc, bmc, -1, nullptr, 2, 1);
    launch_gemm(NN, 192, 64, nullptr, 2, Wgc, nullptr, -1, nullptr, 3, 0);
    // z = relu(gcn_c) + h2 + x1res  (fused) -> B4
    gather_gcn_kernel<<<(NODE192 + BLK - 1) / BLK, BLK>>>(3, bgc, 4, 4, 0, NODE192);

    // ---- attentional aggregation (atomic-free) ----
    launch_gemm(NN, 256, 192, nullptr, 4, Wa1, ba1, -1, nullptr, 2, 1);
    launch_gemm(NN, 192, 256, nullptr, 2, Wa2, ba2, -1, nullptr, 3, 0);
    att_fused_kernel<<<NG, 192>>>(3, 4);

    // ---- decoder ----
    launch_gemm(NG, 192, 192, nullptr, SEL_ZG, Wgd, nullptr, -1, nullptr, SEL_ZGW, 0);
    // B5 = z1_res, B6 = z1_res + pe3 (dual-output epilogue)
    gather_gcn_bcast_kernel<<<(NODE192 + BLK - 1) / BLK, BLK>>>(SEL_ZGW, batch, bgd, 5, pe, 6, NODE192);
    gather_add_kernel<<<(NODE192 + BLK - 1) / BLK, BLK>>>(nullptr, 6, 1, 48, 192, NODE192);
    launch_gemm(NN, 192, 192, nullptr, 1, Wd1, bd1, -1, nullptr, 2, 1);
    gather_add_kernel<<<(NODE192 + BLK - 1) / BLK, BLK>>>(nullptr, 2, 1, 48, 192, NODE192);
    launch_gemm(NN, 192, 192, nullptr, 1, Wd2, bd2, 5, nullptr, 3, 1);
    gather_add_kernel<<<(NODE192 + BLK - 1) / BLK, BLK>>>(nullptr, 3, 1, 48, 192, NODE192);
    launch_gemm(NN, 384, 192, nullptr, 1, Wd3, bd3, -1, out, -1, 1);
}